// round 1
// baseline (speedup 1.0000x reference)
#include <cuda_runtime.h>
#include <math.h>

// Problem constants
#define Bb   4
#define Tt   2048
#define Cc   2048
#define Hh   32
#define Nn   64
#define BT   (Bb*Tt)          // 8192
#define DMIX 32
#define DDEC 64
#define BIGN (BT*Cc)          // 16,777,216

// ---------------- scratch (device globals; no runtime allocation) ----------
__device__ float g_dxprev[BIGN];
__device__ float g_xxx  [BIGN];
__device__ float g_xr   [BIGN];
__device__ float g_xk   [BIGN];
__device__ float g_xv   [BIGN];
__device__ float g_xw   [BIGN];
__device__ float g_xv2  [BIGN];
__device__ float g_r    [BIGN];
__device__ float g_k    [BIGN];
__device__ float g_v    [BIGN];
__device__ float g_v2   [BIGN];
__device__ float g_decay[BIGN];
__device__ float g_ys   [BIGN];
__device__ float g_ynorm[BIGN];
__device__ float g_hpre [BT*160];   // tanh(xxx @ maa_w1)
__device__ float g_tmpw [BT*DDEC];  // tanh(xw  @ decay_w1)
__device__ float g_tmpv [BT*DDEC];  // tanh(xv2 @ value2_w1)

// ---------------- E1: token shift ------------------------------------------
__global__ void k_shift(const float* __restrict__ x,
                        const float* __restrict__ shift,
                        const float* __restrict__ maa_x) {
    int idx = blockIdx.x * 256 + threadIdx.x;
    if (idx >= BIGN) return;
    int c  = idx % Cc;
    int bt = idx / Cc;
    int t  = bt % Tt;
    int b  = bt / Tt;
    float xv   = x[idx];
    float prev = (t == 0) ? shift[b * Cc + c] : x[idx - Cc];
    float dx   = prev - xv;
    g_dxprev[idx] = dx;
    g_xxx[idx]    = xv + dx * maa_x[c];
}

// ---------------- generic SGEMM: C[M,N] = act(A[M,K(lda)] * B[K,N(ldb)]) ----
// BM=128 BN=128 BK=8, 256 threads, 8x8 per thread. M,K multiples of 128/8.
// N arbitrary multiple of 4 (bounds-checked).
__global__ void k_sgemm(const float* __restrict__ A, int lda,
                        const float* __restrict__ B, int ldb,
                        float* __restrict__ Cd, int ldc,
                        int M, int N, int K, int act) {
    __shared__ float As[8][128];
    __shared__ float Bs[8][128];
    int tid = threadIdx.x;
    int tx = tid % 16, ty = tid / 16;
    int nBase = blockIdx.x * 128;
    int mBase = blockIdx.y * 128;

    float acc[8][8];
#pragma unroll
    for (int i = 0; i < 8; i++)
#pragma unroll
        for (int j = 0; j < 8; j++) acc[i][j] = 0.f;

    int aRow  = tid >> 1;          // 0..127
    int aCol4 = (tid & 1) * 4;     // 0 or 4
    int bRow  = tid >> 5;          // 0..7
    int bCol4 = (tid & 31) * 4;    // 0..124

    const float* Ab = A + (size_t)(mBase + aRow) * lda + aCol4;

    for (int k0 = 0; k0 < K; k0 += 8) {
        float4 a4 = *(const float4*)(Ab + k0);
        As[aCol4 + 0][aRow] = a4.x;
        As[aCol4 + 1][aRow] = a4.y;
        As[aCol4 + 2][aRow] = a4.z;
        As[aCol4 + 3][aRow] = a4.w;

        float4 b4 = make_float4(0.f, 0.f, 0.f, 0.f);
        int ncol = nBase + bCol4;
        if (ncol < N)  // N % 4 == 0 guaranteed
            b4 = *(const float4*)(B + (size_t)(k0 + bRow) * ldb + ncol);
        *(float4*)&Bs[bRow][bCol4] = b4;

        __syncthreads();
#pragma unroll
        for (int kk = 0; kk < 8; kk++) {
            float ar[8], br[8];
            *(float4*)&ar[0] = *(const float4*)&As[kk][ty * 8];
            *(float4*)&ar[4] = *(const float4*)&As[kk][ty * 8 + 4];
            *(float4*)&br[0] = *(const float4*)&Bs[kk][tx * 8];
            *(float4*)&br[4] = *(const float4*)&Bs[kk][tx * 8 + 4];
#pragma unroll
            for (int i = 0; i < 8; i++)
#pragma unroll
                for (int j = 0; j < 8; j++)
                    acc[i][j] += ar[i] * br[j];
        }
        __syncthreads();
    }

#pragma unroll
    for (int i = 0; i < 8; i++) {
        int row = mBase + ty * 8 + i;
#pragma unroll
        for (int j = 0; j < 8; j++) {
            int col = nBase + tx * 8 + j;
            if (col < N) {
                float vv = acc[i][j];
                if (act == 1) vv = tanhf(vv);
                Cd[(size_t)row * ldc + col] = vv;
            }
        }
    }
}

// ---------------- E2: 5-way LoRA mix -> xr,xk,xv,xw,xv2 --------------------
// mix_f[bt,c] = sum_d hpre[bt, f*32+d] * w2[(f*32+d)*C + c]
__global__ void k_mix(const float* __restrict__ x,
                      const float* __restrict__ w2,
                      const float* __restrict__ mr, const float* __restrict__ mk,
                      const float* __restrict__ mv, const float* __restrict__ mw,
                      const float* __restrict__ mv2) {
    __shared__ float hs[32][160];
    __shared__ float ws[160][32];
    int rowBase = blockIdx.x * 32;
    int colBase = blockIdx.y * 32;
    int tid = threadIdx.x;

    for (int l = tid; l < 32 * 160; l += 256) {
        int rr = l / 160, d = l % 160;
        hs[rr][d] = g_hpre[(rowBase + rr) * 160 + d];
    }
    for (int l = tid; l < 160 * 32; l += 256) {
        int fd = l / 32, cc = l % 32;
        ws[fd][cc] = w2[fd * Cc + colBase + cc];
    }
    __syncthreads();

    int cc = tid % 32;
    int r0 = tid / 32;
    int c  = colBase + cc;
    float tr = mr[c], tk = mk[c], tv = mv[c], tw = mw[c], tv2 = mv2[c];

    for (int rr = r0; rr < 32; rr += 8) {
        float m0 = 0, m1 = 0, m2 = 0, m3 = 0, m4 = 0;
#pragma unroll
        for (int d = 0; d < 32; d++) {
            float h0 = hs[rr][d];
            float h1 = hs[rr][32 + d];
            float h2 = hs[rr][64 + d];
            float h3 = hs[rr][96 + d];
            float h4 = hs[rr][128 + d];
            m0 += h0 * ws[d][cc];
            m1 += h1 * ws[32 + d][cc];
            m2 += h2 * ws[64 + d][cc];
            m3 += h3 * ws[96 + d][cc];
            m4 += h4 * ws[128 + d][cc];
        }
        int idx = (rowBase + rr) * Cc + c;
        float xv = x[idx], dx = g_dxprev[idx];
        g_xr[idx]  = xv + dx * (tr  + m0);
        g_xk[idx]  = xv + dx * (tk  + m1);
        g_xv[idx]  = xv + dx * (tv  + m2);
        g_xw[idx]  = xv + dx * (tw  + m3);
        g_xv2[idx] = xv + dx * (tv2 + m4);
    }
}

// ---------------- E3: decay = exp(-exp(time_decay + tmpw@decay_w2)); k *= 1-decay
__global__ void k_decay(const float* __restrict__ tdec,
                        const float* __restrict__ w2) {
    __shared__ float tw[32][64];
    __shared__ float w2s[64][64];
    int rowBase = blockIdx.x * 32;
    int colBase = blockIdx.y * 64;
    int tid = threadIdx.x;

    for (int l = tid; l < 32 * 64; l += 256) {
        int rr = l / 64, d = l % 64;
        tw[rr][d] = g_tmpw[(rowBase + rr) * 64 + d];
    }
    for (int l = tid; l < 64 * 64; l += 256) {
        int d = l / 64, cc = l % 64;
        w2s[d][cc] = w2[d * Cc + colBase + cc];
    }
    __syncthreads();

    int cc = tid % 64;
    int r0 = tid / 64;
    float td = tdec[colBase + cc];
    for (int rr = r0; rr < 32; rr += 4) {
        float s = td;
#pragma unroll
        for (int d = 0; d < 64; d++) s += tw[rr][d] * w2s[d][cc];
        float dec = expf(-expf(s));
        int idx = (rowBase + rr) * Cc + colBase + cc;
        g_decay[idx] = dec;
        g_k[idx] *= (1.f - dec);
    }
}

// ---------------- E4: v2 += tmpv @ value2_w2 --------------------------------
__global__ void k_v2add(const float* __restrict__ w2) {
    __shared__ float tw[32][64];
    __shared__ float w2s[64][64];
    int rowBase = blockIdx.x * 32;
    int colBase = blockIdx.y * 64;
    int tid = threadIdx.x;

    for (int l = tid; l < 32 * 64; l += 256) {
        int rr = l / 64, d = l % 64;
        tw[rr][d] = g_tmpv[(rowBase + rr) * 64 + d];
    }
    for (int l = tid; l < 64 * 64; l += 256) {
        int d = l / 64, cc = l % 64;
        w2s[d][cc] = w2[d * Cc + colBase + cc];
    }
    __syncthreads();

    int cc = tid % 64;
    int r0 = tid / 64;
    for (int rr = r0; rr < 32; rr += 4) {
        float s = 0.f;
#pragma unroll
        for (int d = 0; d < 64; d++) s += tw[rr][d] * w2s[d][cc];
        int idx = (rowBase + rr) * Cc + colBase + cc;
        g_v2[idx] += s;
    }
}

// ---------------- S: WKV scan over T ---------------------------------------
// block = (h, b); 64 threads; thread j owns state column j (64 rows in regs).
__global__ void k_scan(const float* __restrict__ wkv_in,
                       float* __restrict__ wkv_out) {
    int h = blockIdx.x, b = blockIdx.y;
    int j = threadIdx.x;

    float state[64];
#pragma unroll
    for (int i = 0; i < 64; i++)
        state[i] = wkv_in[(size_t)((b * Hh + h) * Nn + i) * Nn + j];

    __shared__ float rs[64], ks[64], ds[64];
    const float4* rs4 = (const float4*)rs;
    const float4* ks4 = (const float4*)ks;
    const float4* ds4 = (const float4*)ds;

    for (int t = 0; t < Tt; t++) {
        int base = (b * Tt + t) * Cc + h * Nn;
        rs[j] = g_r[base + j];
        ks[j] = g_k[base + j];
        ds[j] = g_decay[base + j];
        float vj = g_v[base + j];
        __syncthreads();
        float y = 0.f;
#pragma unroll
        for (int i4 = 0; i4 < 16; i4++) {
            float4 r4 = rs4[i4], k4 = ks4[i4], d4 = ds4[i4];
            float s0 = state[4 * i4 + 0], s1 = state[4 * i4 + 1];
            float s2 = state[4 * i4 + 2], s3 = state[4 * i4 + 3];
            y += r4.x * s0; y += r4.y * s1; y += r4.z * s2; y += r4.w * s3;
            state[4 * i4 + 0] = s0 * d4.x + k4.x * vj;
            state[4 * i4 + 1] = s1 * d4.y + k4.y * vj;
            state[4 * i4 + 2] = s2 * d4.z + k4.z * vj;
            state[4 * i4 + 3] = s3 * d4.w + k4.w * vj;
        }
        g_ys[base + j] = y;
        __syncthreads();
    }

#pragma unroll
    for (int i = 0; i < 64; i++)
        wkv_out[(size_t)((b * Hh + h) * Nn + i) * Nn + j] = state[i];
}

// ---------------- E5: y = LN(ys + v2) ---------------------------------------
__global__ void k_ln(const float* __restrict__ lnw,
                     const float* __restrict__ lnb) {
    int row = blockIdx.x;
    int tid = threadIdx.x;
    const float* a = g_ys + (size_t)row * Cc;
    const float* bp = g_v2 + (size_t)row * Cc;
    float s = 0.f, ss = 0.f;
    for (int c = tid; c < Cc; c += 256) {
        float v = a[c] + bp[c];
        s += v; ss += v * v;
    }
    __shared__ float sh1[256], sh2[256];
    sh1[tid] = s; sh2[tid] = ss;
    __syncthreads();
    for (int st = 128; st > 0; st >>= 1) {
        if (tid < st) { sh1[tid] += sh1[tid + st]; sh2[tid] += sh2[tid + st]; }
        __syncthreads();
    }
    float mu  = sh1[0] / Cc;
    float var = sh2[0] / Cc - mu * mu;
    float rstd = rsqrtf(var + 1e-5f);
    for (int c = tid; c < Cc; c += 256) {
        float v = a[c] + bp[c];
        g_ynorm[(size_t)row * Cc + c] = (v - mu) * rstd * lnw[c] + lnb[c];
    }
}

// ---------------- E6: shift_state_out = x[:, -1, :] --------------------------
__global__ void k_copyshift(const float* __restrict__ x, float* __restrict__ out) {
    int i = blockIdx.x * 256 + threadIdx.x;
    if (i >= Bb * Cc) return;
    int b = i / Cc, c = i % Cc;
    out[i] = x[(size_t)(b * Tt + Tt - 1) * Cc + c];
}

// ---------------- launcher ---------------------------------------------------
extern "C" void kernel_launch(void* const* d_in, const int* in_sizes, int n_in,
                              void* d_out, int out_size) {
    const float* x        = (const float*)d_in[0];
    const float* shift_in = (const float*)d_in[1];
    const float* wkv_in   = (const float*)d_in[2];
    const float* maa_x    = (const float*)d_in[3];
    const float* maa_r    = (const float*)d_in[4];
    const float* maa_k    = (const float*)d_in[5];
    const float* maa_v    = (const float*)d_in[6];
    const float* maa_w    = (const float*)d_in[7];
    const float* maa_v2   = (const float*)d_in[8];
    const float* maa_w1   = (const float*)d_in[9];   // [C,160]
    const float* maa_w2   = (const float*)d_in[10];  // [5,32,C]
    const float* tdecay   = (const float*)d_in[11];  // [C]
    const float* dec_w1   = (const float*)d_in[12];  // [C,64]
    const float* dec_w2   = (const float*)d_in[13];  // [64,C]
    const float* v2_w1    = (const float*)d_in[14];  // [C,64]
    const float* v2_w2    = (const float*)d_in[15];  // [64,C]
    const float* W_r      = (const float*)d_in[16];
    const float* W_k      = (const float*)d_in[17];
    const float* W_v      = (const float*)d_in[18];
    const float* W_o      = (const float*)d_in[19];
    const float* ln_w     = (const float*)d_in[20];
    const float* ln_b     = (const float*)d_in[21];

    float* out_y     = (float*)d_out;
    float* out_shift = out_y + (size_t)BT * Cc;
    float* out_wkv   = out_shift + (size_t)Bb * Cc;

    float *dxprev, *xxx, *xr, *xk, *xv, *xw, *xv2;
    float *rb, *kb, *vb, *v2b, *hpre, *tmpw, *tmpv, *ynorm;
    cudaGetSymbolAddress((void**)&dxprev, g_dxprev);
    cudaGetSymbolAddress((void**)&xxx,    g_xxx);
    cudaGetSymbolAddress((void**)&xr,     g_xr);
    cudaGetSymbolAddress((void**)&xk,     g_xk);
    cudaGetSymbolAddress((void**)&xv,     g_xv);
    cudaGetSymbolAddress((void**)&xw,     g_xw);
    cudaGetSymbolAddress((void**)&xv2,    g_xv2);
    cudaGetSymbolAddress((void**)&rb,     g_r);
    cudaGetSymbolAddress((void**)&kb,     g_k);
    cudaGetSymbolAddress((void**)&vb,     g_v);
    cudaGetSymbolAddress((void**)&v2b,    g_v2);
    cudaGetSymbolAddress((void**)&hpre,   g_hpre);
    cudaGetSymbolAddress((void**)&tmpw,   g_tmpw);
    cudaGetSymbolAddress((void**)&tmpv,   g_tmpv);
    cudaGetSymbolAddress((void**)&ynorm,  g_ynorm);

    // E1: token shift
    k_shift<<<BIGN / 256, 256>>>(x, shift_in, maa_x);

    // G1: hpre = tanh(xxx @ maa_w1)  [8192,160]
    k_sgemm<<<dim3(2, BT / 128), 256>>>(xxx, Cc, maa_w1, 160, hpre, 160,
                                        BT, 160, Cc, 1);

    // E2: 5-way mix
    k_mix<<<dim3(BT / 32, Cc / 32), 256>>>(x, maa_w2, maa_r, maa_k, maa_v,
                                           maa_w, maa_v2);

    // Big GEMMs
    k_sgemm<<<dim3(16, BT / 128), 256>>>(xr,  Cc, W_r, Cc, rb,  Cc, BT, Cc, Cc, 0);
    k_sgemm<<<dim3(16, BT / 128), 256>>>(xk,  Cc, W_k, Cc, kb,  Cc, BT, Cc, Cc, 0);
    k_sgemm<<<dim3(16, BT / 128), 256>>>(xv,  Cc, W_v, Cc, vb,  Cc, BT, Cc, Cc, 0);
    k_sgemm<<<dim3(16, BT / 128), 256>>>(xv2, Cc, W_v, Cc, v2b, Cc, BT, Cc, Cc, 0);

    // Small LoRA GEMMs (tanh)
    k_sgemm<<<dim3(1, BT / 128), 256>>>(xw,  Cc, dec_w1, 64, tmpw, 64, BT, 64, Cc, 1);
    k_sgemm<<<dim3(1, BT / 128), 256>>>(xv2, Cc, v2_w1,  64, tmpv, 64, BT, 64, Cc, 1);

    // E3/E4 epilogues
    k_decay<<<dim3(BT / 32, Cc / 64), 256>>>(tdecay, dec_w2);
    k_v2add<<<dim3(BT / 32, Cc / 64), 256>>>(v2_w2);

    // WKV scan
    k_scan<<<dim3(Hh, Bb), 64>>>(wkv_in, out_wkv);

    // LayerNorm(ys + v2)
    k_ln<<<BT, 256>>>(ln_w, ln_b);

    // Output GEMM: y = ynorm @ W_o -> d_out region 0
    k_sgemm<<<dim3(16, BT / 128), 256>>>(ynorm, Cc, W_o, Cc, out_y, Cc,
                                         BT, Cc, Cc, 0);

    // shift state out
    k_copyshift<<<(Bb * Cc + 255) / 256, 256>>>(x, out_shift);
}

// round 3
// speedup vs baseline: 1.7119x; 1.7119x over previous
#include <cuda_runtime.h>
#include <cuda_bf16.h>
#include <cstdint>
#include <cstdio>
#include <math.h>

// Problem constants
#define Bb   4
#define Tt   2048
#define Cc   2048
#define Hh   32
#define Nn   64
#define BT   (Bb*Tt)          // 8192
#define DMIX 32
#define DDEC 64
#define BIGN (BT*Cc)          // 16,777,216

// ---------------- scratch (device globals; no runtime allocation) ----------
__device__ float g_dxprev[BIGN];
__device__ float g_xxx  [BIGN];
__device__ float g_xr   [BIGN];
__device__ float g_xk   [BIGN];
__device__ float g_xv   [BIGN];
__device__ float g_xw   [BIGN];
__device__ float g_xv2  [BIGN];
__device__ float g_r    [BIGN];
__device__ float g_k    [BIGN];
__device__ float g_v    [BIGN];
__device__ float g_v2   [BIGN];
__device__ float g_decay[BIGN];
__device__ float g_ys   [BIGN];
__device__ float g_ynorm[BIGN];
__device__ float g_hpre [BT*160];   // tanh(xxx @ maa_w1)
__device__ float g_tmpw [BT*DDEC];  // tanh(xw  @ decay_w1)
__device__ float g_tmpv [BT*DDEC];  // tanh(xv2 @ value2_w1)

// ---------------- E1: token shift ------------------------------------------
__global__ void k_shift(const float* __restrict__ x,
                        const float* __restrict__ shift,
                        const float* __restrict__ maa_x) {
    int idx = blockIdx.x * 256 + threadIdx.x;
    if (idx >= BIGN) return;
    int c  = idx % Cc;
    int bt = idx / Cc;
    int t  = bt % Tt;
    int b  = bt / Tt;
    float xv   = x[idx];
    float prev = (t == 0) ? shift[b * Cc + c] : x[idx - Cc];
    float dx   = prev - xv;
    g_dxprev[idx] = dx;
    g_xxx[idx]    = xv + dx * maa_x[c];
}

// =============================================================================
// Tensor-core GEMM (bf16x3 split, fp32 accumulate):
// C[M,N] = A[M,K] * B[K,N], all fp32 in global. M%128==0, N%128==0, K%32==0.
// CTA tile 128x128, BK=32 fp32. 8 warps, each 64x32. Double-buffered smem.
// a*b ~= a_hi*b_hi + a_hi*b_lo + a_lo*b_hi  (per-element err ~2^-16)
// =============================================================================
#define ASTR 40     // bf16 row stride for A tiles (128 rows x 32+pad)
#define BSTR 136    // bf16 row stride for B tiles (32 rows x 128+pad)
#define SA_H 0
#define SA_L 5120       // 128*40
#define SB_H 10240      // 2*128*40
#define SB_L 14592      // +32*136
#define STG  18944      // bf16 elems per stage
#define STG_BYTES (STG*2)

__device__ __forceinline__ void ldsm4(unsigned int* r, unsigned int addr) {
    asm volatile("ldmatrix.sync.aligned.m8n8.x4.shared.b16 {%0,%1,%2,%3},[%4];"
                 : "=r"(r[0]), "=r"(r[1]), "=r"(r[2]), "=r"(r[3]) : "r"(addr));
}
__device__ __forceinline__ void ldsm4t(unsigned int* r, unsigned int addr) {
    asm volatile("ldmatrix.sync.aligned.m8n8.x4.trans.shared.b16 {%0,%1,%2,%3},[%4];"
                 : "=r"(r[0]), "=r"(r[1]), "=r"(r[2]), "=r"(r[3]) : "r"(addr));
}
__device__ __forceinline__ void mma16816(float* c, const unsigned int* a,
                                         unsigned int b0, unsigned int b1) {
    asm volatile("mma.sync.aligned.m16n8k16.row.col.f32.bf16.bf16.f32 "
                 "{%0,%1,%2,%3},{%4,%5,%6,%7},{%8,%9},{%0,%1,%2,%3};"
                 : "+f"(c[0]), "+f"(c[1]), "+f"(c[2]), "+f"(c[3])
                 : "r"(a[0]), "r"(a[1]), "r"(a[2]), "r"(a[3]), "r"(b0), "r"(b1));
}

__device__ __forceinline__ void split2(float f, __nv_bfloat16& h, __nv_bfloat16& l) {
    h = __float2bfloat16_rn(f);
    l = __float2bfloat16_rn(f - __bfloat162float(h));
}

__global__ __launch_bounds__(256, 1)
void k_mma_gemm(const float* __restrict__ A,
                const float* __restrict__ B,
                float* __restrict__ C,
                int M, int N, int K) {
    extern __shared__ __nv_bfloat16 smbuf[];
    const int tid  = threadIdx.x;
    const int lane = tid & 31;
    const int wid  = tid >> 5;
    const int wm   = wid >> 2;        // 0..1 : warp m offset = wm*64
    const int wn   = wid & 3;         // 0..3 : warp n offset = wn*32
    const int mBase = blockIdx.y * 128;
    const int nBase = blockIdx.x * 128;

    const unsigned int smB = (unsigned int)__cvta_generic_to_shared(smbuf);

    // global load mapping
    const int arow = tid >> 3;          // 0..31 (pass stride 32)
    const int acol = (tid & 7) * 4;     // 0..28
    const int brow = tid >> 5;          // 0..7  (pass stride 8)
    const int bcol = (tid & 31) * 4;    // 0..124

    const float* Ap = A + (size_t)(mBase + arow) * K + acol;
    const float* Bp = B + (size_t)brow * N + nBase + bcol;

    float acc[4][4][4];
#pragma unroll
    for (int i = 0; i < 4; i++)
#pragma unroll
        for (int j = 0; j < 4; j++)
#pragma unroll
            for (int q = 0; q < 4; q++) acc[i][j][q] = 0.f;

    float4 aR[4], bR[4];
    const int kChunks = K >> 5;

    // prologue: load chunk 0
#pragma unroll
    for (int p = 0; p < 4; p++) aR[p] = *(const float4*)(Ap + (size_t)(p * 32) * K);
#pragma unroll
    for (int p = 0; p < 4; p++) bR[p] = *(const float4*)(Bp + (size_t)(p * 8) * N);

    // store chunk 0 to stage 0
    {
        __nv_bfloat16* st = smbuf;
#pragma unroll
        for (int p = 0; p < 4; p++) {
            int row = arow + p * 32;
            __nv_bfloat16 h0,h1,h2,h3,l0,l1,l2,l3;
            split2(aR[p].x,h0,l0); split2(aR[p].y,h1,l1);
            split2(aR[p].z,h2,l2); split2(aR[p].w,h3,l3);
            __nv_bfloat162 *ph = (__nv_bfloat162*)(st + SA_H + row*ASTR + acol);
            __nv_bfloat162 *pl = (__nv_bfloat162*)(st + SA_L + row*ASTR + acol);
            ph[0] = __halves2bfloat162(h0,h1); ph[1] = __halves2bfloat162(h2,h3);
            pl[0] = __halves2bfloat162(l0,l1); pl[1] = __halves2bfloat162(l2,l3);
        }
#pragma unroll
        for (int p = 0; p < 4; p++) {
            int row = brow + p * 8;
            __nv_bfloat16 h0,h1,h2,h3,l0,l1,l2,l3;
            split2(bR[p].x,h0,l0); split2(bR[p].y,h1,l1);
            split2(bR[p].z,h2,l2); split2(bR[p].w,h3,l3);
            __nv_bfloat162 *ph = (__nv_bfloat162*)(st + SB_H + row*BSTR + bcol);
            __nv_bfloat162 *pl = (__nv_bfloat162*)(st + SB_L + row*BSTR + bcol);
            ph[0] = __halves2bfloat162(h0,h1); ph[1] = __halves2bfloat162(h2,h3);
            pl[0] = __halves2bfloat162(l0,l1); pl[1] = __halves2bfloat162(l2,l3);
        }
    }
    __syncthreads();

#pragma unroll 1
    for (int ch = 0; ch < kChunks; ch++) {
        const int cur = ch & 1;
        const bool more = (ch + 1) < kChunks;

        // prefetch next chunk (global -> regs)
        if (more) {
            const float* Apn = Ap + (ch + 1) * 32;
            const float* Bpn = Bp + (size_t)(ch + 1) * 32 * N;
#pragma unroll
            for (int p = 0; p < 4; p++) aR[p] = *(const float4*)(Apn + (size_t)(p * 32) * K);
#pragma unroll
            for (int p = 0; p < 4; p++) bR[p] = *(const float4*)(Bpn + (size_t)(p * 8) * N);
        }

        // compute on current stage
        const unsigned int sb = smB + cur * STG_BYTES;
#pragma unroll
        for (int ks = 0; ks < 2; ks++) {
            const int k0 = ks * 16;
            unsigned int ah[4][4], al[4][4], bh[2][4], bl[2][4];
#pragma unroll
            for (int mf = 0; mf < 4; mf++) {
                int row = wm * 64 + mf * 16 + (lane & 15);
                int col = k0 + (lane >> 4) * 8;
                unsigned int ad = sb + (unsigned int)(row * ASTR + col) * 2;
                ldsm4(ah[mf], ad + SA_H * 2);
                ldsm4(al[mf], ad + SA_L * 2);
            }
#pragma unroll
            for (int nf2 = 0; nf2 < 2; nf2++) {
                int rowk = k0 + (lane & 15);
                int coln = wn * 32 + nf2 * 16 + (lane >> 4) * 8;
                unsigned int bd = sb + (unsigned int)(rowk * BSTR + coln) * 2;
                ldsm4t(bh[nf2], bd + SB_H * 2);
                ldsm4t(bl[nf2], bd + SB_L * 2);
            }
#pragma unroll
            for (int mf = 0; mf < 4; mf++) {
#pragma unroll
                for (int nf = 0; nf < 4; nf++) {
                    unsigned int b0h = bh[nf >> 1][(nf & 1) * 2];
                    unsigned int b1h = bh[nf >> 1][(nf & 1) * 2 + 1];
                    unsigned int b0l = bl[nf >> 1][(nf & 1) * 2];
                    unsigned int b1l = bl[nf >> 1][(nf & 1) * 2 + 1];
                    mma16816(acc[mf][nf], ah[mf], b0h, b1h);
                    mma16816(acc[mf][nf], ah[mf], b0l, b1l);
                    mma16816(acc[mf][nf], al[mf], b0h, b1h);
                }
            }
        }

        // store prefetched regs into next stage
        if (more) {
            __nv_bfloat16* st = smbuf + (cur ^ 1) * STG;
#pragma unroll
            for (int p = 0; p < 4; p++) {
                int row = arow + p * 32;
                __nv_bfloat16 h0,h1,h2,h3,l0,l1,l2,l3;
                split2(aR[p].x,h0,l0); split2(aR[p].y,h1,l1);
                split2(aR[p].z,h2,l2); split2(aR[p].w,h3,l3);
                __nv_bfloat162 *ph = (__nv_bfloat162*)(st + SA_H + row*ASTR + acol);
                __nv_bfloat162 *pl = (__nv_bfloat162*)(st + SA_L + row*ASTR + acol);
                ph[0] = __halves2bfloat162(h0,h1); ph[1] = __halves2bfloat162(h2,h3);
                pl[0] = __halves2bfloat162(l0,l1); pl[1] = __halves2bfloat162(l2,l3);
            }
#pragma unroll
            for (int p = 0; p < 4; p++) {
                int row = brow + p * 8;
                __nv_bfloat16 h0,h1,h2,h3,l0,l1,l2,l3;
                split2(bR[p].x,h0,l0); split2(bR[p].y,h1,l1);
                split2(bR[p].z,h2,l2); split2(bR[p].w,h3,l3);
                __nv_bfloat162 *ph = (__nv_bfloat162*)(st + SB_H + row*BSTR + bcol);
                __nv_bfloat162 *pl = (__nv_bfloat162*)(st + SB_L + row*BSTR + bcol);
                ph[0] = __halves2bfloat162(h0,h1); ph[1] = __halves2bfloat162(h2,h3);
                pl[0] = __halves2bfloat162(l0,l1); pl[1] = __halves2bfloat162(l2,l3);
            }
        }
        __syncthreads();
    }

    // epilogue
#pragma unroll
    for (int mf = 0; mf < 4; mf++) {
#pragma unroll
        for (int nf = 0; nf < 4; nf++) {
            int r = mBase + wm * 64 + mf * 16 + (lane >> 2);
            int c = nBase + wn * 32 + nf * 8 + (lane & 3) * 2;
            float2 v0 = make_float2(acc[mf][nf][0], acc[mf][nf][1]);
            float2 v1 = make_float2(acc[mf][nf][2], acc[mf][nf][3]);
            *(float2*)&C[(size_t)r * N + c] = v0;
            *(float2*)&C[(size_t)(r + 8) * N + c] = v1;
        }
    }
}

// ---------------- generic fp32 SGEMM (kept for small LoRA matmuls) ----------
__global__ void k_sgemm(const float* __restrict__ A, int lda,
                        const float* __restrict__ B, int ldb,
                        float* __restrict__ Cd, int ldc,
                        int M, int N, int K, int act) {
    __shared__ float As[8][128];
    __shared__ float Bs[8][128];
    int tid = threadIdx.x;
    int tx = tid % 16, ty = tid / 16;
    int nBase = blockIdx.x * 128;
    int mBase = blockIdx.y * 128;

    float acc[8][8];
#pragma unroll
    for (int i = 0; i < 8; i++)
#pragma unroll
        for (int j = 0; j < 8; j++) acc[i][j] = 0.f;

    int aRow  = tid >> 1;
    int aCol4 = (tid & 1) * 4;
    int bRow  = tid >> 5;
    int bCol4 = (tid & 31) * 4;

    const float* Ab = A + (size_t)(mBase + aRow) * lda + aCol4;

    for (int k0 = 0; k0 < K; k0 += 8) {
        float4 a4 = *(const float4*)(Ab + k0);
        As[aCol4 + 0][aRow] = a4.x;
        As[aCol4 + 1][aRow] = a4.y;
        As[aCol4 + 2][aRow] = a4.z;
        As[aCol4 + 3][aRow] = a4.w;

        float4 b4 = make_float4(0.f, 0.f, 0.f, 0.f);
        int ncol = nBase + bCol4;
        if (ncol < N)
            b4 = *(const float4*)(B + (size_t)(k0 + bRow) * ldb + ncol);
        *(float4*)&Bs[bRow][bCol4] = b4;

        __syncthreads();
#pragma unroll
        for (int kk = 0; kk < 8; kk++) {
            float ar[8], br[8];
            *(float4*)&ar[0] = *(const float4*)&As[kk][ty * 8];
            *(float4*)&ar[4] = *(const float4*)&As[kk][ty * 8 + 4];
            *(float4*)&br[0] = *(const float4*)&Bs[kk][tx * 8];
            *(float4*)&br[4] = *(const float4*)&Bs[kk][tx * 8 + 4];
#pragma unroll
            for (int i = 0; i < 8; i++)
#pragma unroll
                for (int j = 0; j < 8; j++)
                    acc[i][j] += ar[i] * br[j];
        }
        __syncthreads();
    }

#pragma unroll
    for (int i = 0; i < 8; i++) {
        int row = mBase + ty * 8 + i;
#pragma unroll
        for (int j = 0; j < 8; j++) {
            int col = nBase + tx * 8 + j;
            if (col < N) {
                float vv = acc[i][j];
                if (act == 1) vv = tanhf(vv);
                Cd[(size_t)row * ldc + col] = vv;
            }
        }
    }
}

// ---------------- E2: 5-way LoRA mix -> xr,xk,xv,xw,xv2 --------------------
__global__ void k_mix(const float* __restrict__ x,
                      const float* __restrict__ w2,
                      const float* __restrict__ mr, const float* __restrict__ mk,
                      const float* __restrict__ mv, const float* __restrict__ mw,
                      const float* __restrict__ mv2) {
    __shared__ float hs[32][160];
    __shared__ float ws[160][32];
    int rowBase = blockIdx.x * 32;
    int colBase = blockIdx.y * 32;
    int tid = threadIdx.x;

    for (int l = tid; l < 32 * 160; l += 256) {
        int rr = l / 160, d = l % 160;
        hs[rr][d] = g_hpre[(rowBase + rr) * 160 + d];
    }
    for (int l = tid; l < 160 * 32; l += 256) {
        int fd = l / 32, cc = l % 32;
        ws[fd][cc] = w2[fd * Cc + colBase + cc];
    }
    __syncthreads();

    int cc = tid % 32;
    int r0 = tid / 32;
    int c  = colBase + cc;
    float tr = mr[c], tk = mk[c], tv = mv[c], tw = mw[c], tv2 = mv2[c];

    for (int rr = r0; rr < 32; rr += 8) {
        float m0 = 0, m1 = 0, m2 = 0, m3 = 0, m4 = 0;
#pragma unroll
        for (int d = 0; d < 32; d++) {
            float h0 = hs[rr][d];
            float h1 = hs[rr][32 + d];
            float h2 = hs[rr][64 + d];
            float h3 = hs[rr][96 + d];
            float h4 = hs[rr][128 + d];
            m0 += h0 * ws[d][cc];
            m1 += h1 * ws[32 + d][cc];
            m2 += h2 * ws[64 + d][cc];
            m3 += h3 * ws[96 + d][cc];
            m4 += h4 * ws[128 + d][cc];
        }
        int idx = (rowBase + rr) * Cc + c;
        float xv = x[idx], dx = g_dxprev[idx];
        g_xr[idx]  = xv + dx * (tr  + m0);
        g_xk[idx]  = xv + dx * (tk  + m1);
        g_xv[idx]  = xv + dx * (tv  + m2);
        g_xw[idx]  = xv + dx * (tw  + m3);
        g_xv2[idx] = xv + dx * (tv2 + m4);
    }
}

// ---------------- E3: decay = exp(-exp(time_decay + tmpw@decay_w2)); k *= 1-decay
__global__ void k_decay(const float* __restrict__ tdec,
                        const float* __restrict__ w2) {
    __shared__ float tw[32][64];
    __shared__ float w2s[64][64];
    int rowBase = blockIdx.x * 32;
    int colBase = blockIdx.y * 64;
    int tid = threadIdx.x;

    for (int l = tid; l < 32 * 64; l += 256) {
        int rr = l / 64, d = l % 64;
        tw[rr][d] = g_tmpw[(rowBase + rr) * 64 + d];
    }
    for (int l = tid; l < 64 * 64; l += 256) {
        int d = l / 64, cc = l % 64;
        w2s[d][cc] = w2[d * Cc + colBase + cc];
    }
    __syncthreads();

    int cc = tid % 64;
    int r0 = tid / 64;
    float td = tdec[colBase + cc];
    for (int rr = r0; rr < 32; rr += 4) {
        float s = td;
#pragma unroll
        for (int d = 0; d < 64; d++) s += tw[rr][d] * w2s[d][cc];
        float dec = expf(-expf(s));
        int idx = (rowBase + rr) * Cc + colBase + cc;
        g_decay[idx] = dec;
        g_k[idx] *= (1.f - dec);
    }
}

// ---------------- E4: v2 += tmpv @ value2_w2 --------------------------------
__global__ void k_v2add(const float* __restrict__ w2) {
    __shared__ float tw[32][64];
    __shared__ float w2s[64][64];
    int rowBase = blockIdx.x * 32;
    int colBase = blockIdx.y * 64;
    int tid = threadIdx.x;

    for (int l = tid; l < 32 * 64; l += 256) {
        int rr = l / 64, d = l % 64;
        tw[rr][d] = g_tmpv[(rowBase + rr) * 64 + d];
    }
    for (int l = tid; l < 64 * 64; l += 256) {
        int d = l / 64, cc = l % 64;
        w2s[d][cc] = w2[d * Cc + colBase + cc];
    }
    __syncthreads();

    int cc = tid % 64;
    int r0 = tid / 64;
    for (int rr = r0; rr < 32; rr += 4) {
        float s = 0.f;
#pragma unroll
        for (int d = 0; d < 64; d++) s += tw[rr][d] * w2s[d][cc];
        int idx = (rowBase + rr) * Cc + colBase + cc;
        g_v2[idx] += s;
    }
}

// ---------------- S: WKV scan over T ---------------------------------------
__global__ void k_scan(const float* __restrict__ wkv_in,
                       float* __restrict__ wkv_out) {
    int h = blockIdx.x, b = blockIdx.y;
    int j = threadIdx.x;

    float state[64];
#pragma unroll
    for (int i = 0; i < 64; i++)
        state[i] = wkv_in[(size_t)((b * Hh + h) * Nn + i) * Nn + j];

    __shared__ float rs[64], ks[64], ds[64];
    const float4* rs4 = (const float4*)rs;
    const float4* ks4 = (const float4*)ks;
    const float4* ds4 = (const float4*)ds;

    for (int t = 0; t < Tt; t++) {
        int base = (b * Tt + t) * Cc + h * Nn;
        rs[j] = g_r[base + j];
        ks[j] = g_k[base + j];
        ds[j] = g_decay[base + j];
        float vj = g_v[base + j];
        __syncthreads();
        float y = 0.f;
#pragma unroll
        for (int i4 = 0; i4 < 16; i4++) {
            float4 r4 = rs4[i4], k4 = ks4[i4], d4 = ds4[i4];
            float s0 = state[4 * i4 + 0], s1 = state[4 * i4 + 1];
            float s2 = state[4 * i4 + 2], s3 = state[4 * i4 + 3];
            y += r4.x * s0; y += r4.y * s1; y += r4.z * s2; y += r4.w * s3;
            state[4 * i4 + 0] = s0 * d4.x + k4.x * vj;
            state[4 * i4 + 1] = s1 * d4.y + k4.y * vj;
            state[4 * i4 + 2] = s2 * d4.z + k4.z * vj;
            state[4 * i4 + 3] = s3 * d4.w + k4.w * vj;
        }
        g_ys[base + j] = y;
        __syncthreads();
    }

#pragma unroll
    for (int i = 0; i < 64; i++)
        wkv_out[(size_t)((b * Hh + h) * Nn + i) * Nn + j] = state[i];
}

// ---------------- E5: y = LN(ys + v2) ---------------------------------------
__global__ void k_ln(const float* __restrict__ lnw,
                     const float* __restrict__ lnb) {
    int row = blockIdx.x;
    int tid = threadIdx.x;
    const float* a = g_ys + (size_t)row * Cc;
    const float* bp = g_v2 + (size_t)row * Cc;
    float s = 0.f, ss = 0.f;
    for (int c = tid; c < Cc; c += 256) {
        float v = a[c] + bp[c];
        s += v; ss += v * v;
    }
    __shared__ float sh1[256], sh2[256];
    sh1[tid] = s; sh2[tid] = ss;
    __syncthreads();
    for (int st = 128; st > 0; st >>= 1) {
        if (tid < st) { sh1[tid] += sh1[tid + st]; sh2[tid] += sh2[tid + st]; }
        __syncthreads();
    }
    float mu  = sh1[0] / Cc;
    float var = sh2[0] / Cc - mu * mu;
    float rstd = rsqrtf(var + 1e-5f);
    for (int c = tid; c < Cc; c += 256) {
        float v = a[c] + bp[c];
        g_ynorm[(size_t)row * Cc + c] = (v - mu) * rstd * lnw[c] + lnb[c];
    }
}

// ---------------- E6: shift_state_out = x[:, -1, :] --------------------------
__global__ void k_copyshift(const float* __restrict__ x, float* __restrict__ out) {
    int i = blockIdx.x * 256 + threadIdx.x;
    if (i >= Bb * Cc) return;
    int b = i / Cc, c = i % Cc;
    out[i] = x[(size_t)(b * Tt + Tt - 1) * Cc + c];
}

// ---------------- launcher ---------------------------------------------------
extern "C" void kernel_launch(void* const* d_in, const int* in_sizes, int n_in,
                              void* d_out, int out_size) {
    const float* x        = (const float*)d_in[0];
    const float* shift_in = (const float*)d_in[1];
    const float* wkv_in   = (const float*)d_in[2];
    const float* maa_x    = (const float*)d_in[3];
    const float* maa_r    = (const float*)d_in[4];
    const float* maa_k    = (const float*)d_in[5];
    const float* maa_v    = (const float*)d_in[6];
    const float* maa_w    = (const float*)d_in[7];
    const float* maa_v2   = (const float*)d_in[8];
    const float* maa_w1   = (const float*)d_in[9];
    const float* maa_w2   = (const float*)d_in[10];
    const float* tdecay   = (const float*)d_in[11];
    const float* dec_w1   = (const float*)d_in[12];
    const float* dec_w2   = (const float*)d_in[13];
    const float* v2_w1    = (const float*)d_in[14];
    const float* v2_w2    = (const float*)d_in[15];
    const float* W_r      = (const float*)d_in[16];
    const float* W_k      = (const float*)d_in[17];
    const float* W_v      = (const float*)d_in[18];
    const float* W_o      = (const float*)d_in[19];
    const float* ln_w     = (const float*)d_in[20];
    const float* ln_b     = (const float*)d_in[21];

    float* out_y     = (float*)d_out;
    float* out_shift = out_y + (size_t)BT * Cc;
    float* out_wkv   = out_shift + (size_t)Bb * Cc;

    float *xxx = 0, *xr = 0, *xk = 0, *xv = 0, *xw = 0, *xv2 = 0;
    float *rb = 0, *kb = 0, *vb = 0, *v2b = 0, *hpre = 0, *tmpw = 0, *tmpv = 0, *ynorm = 0;
    cudaGetSymbolAddress((void**)&xxx,    g_xxx);
    cudaGetSymbolAddress((void**)&xr,     g_xr);
    cudaGetSymbolAddress((void**)&xk,     g_xk);
    cudaGetSymbolAddress((void**)&xv,     g_xv);
    cudaGetSymbolAddress((void**)&xw,     g_xw);
    cudaGetSymbolAddress((void**)&xv2,    g_xv2);
    cudaGetSymbolAddress((void**)&rb,     g_r);
    cudaGetSymbolAddress((void**)&kb,     g_k);
    cudaGetSymbolAddress((void**)&vb,     g_v);
    cudaGetSymbolAddress((void**)&v2b,    g_v2);
    cudaGetSymbolAddress((void**)&hpre,   g_hpre);
    cudaGetSymbolAddress((void**)&tmpw,   g_tmpw);
    cudaGetSymbolAddress((void**)&tmpv,   g_tmpv);
    cudaGetSymbolAddress((void**)&ynorm,  g_ynorm);

    cudaFuncSetAttribute(k_mma_gemm,
                         cudaFuncAttributeMaxDynamicSharedMemorySize,
                         2 * STG_BYTES);

    const dim3 gemmGrid(Cc / 128, BT / 128);   // (16, 64)
    const int  gemmSmem = 2 * STG_BYTES;

    // E1: token shift
    k_shift<<<BIGN / 256, 256>>>(x, shift_in, maa_x);

    // G1: hpre = tanh(xxx @ maa_w1)  [8192,160]
    k_sgemm<<<dim3(2, BT / 128), 256>>>(xxx, Cc, maa_w1, 160, hpre, 160,
                                        BT, 160, Cc, 1);

    // E2: 5-way mix
    k_mix<<<dim3(BT / 32, Cc / 32), 256>>>(x, maa_w2, maa_r, maa_k, maa_v,
                                           maa_w, maa_v2);

    // Big GEMMs on tensor cores (bf16x3)
    k_mma_gemm<<<gemmGrid, 256, gemmSmem>>>(xr,  W_r, rb,  BT, Cc, Cc);
    k_mma_gemm<<<gemmGrid, 256, gemmSmem>>>(xk,  W_k, kb,  BT, Cc, Cc);
    k_mma_gemm<<<gemmGrid, 256, gemmSmem>>>(xv,  W_v, vb,  BT, Cc, Cc);
    k_mma_gemm<<<gemmGrid, 256, gemmSmem>>>(xv2, W_v, v2b, BT, Cc, Cc);

    // Small LoRA GEMMs (tanh)
    k_sgemm<<<dim3(1, BT / 128), 256>>>(xw,  Cc, dec_w1, 64, tmpw, 64, BT, 64, Cc, 1);
    k_sgemm<<<dim3(1, BT / 128), 256>>>(xv2, Cc, v2_w1,  64, tmpv, 64, BT, 64, Cc, 1);

    // E3/E4 epilogues
    k_decay<<<dim3(BT / 32, Cc / 64), 256>>>(tdecay, dec_w2);
    k_v2add<<<dim3(BT / 32, Cc / 64), 256>>>(v2_w2);

    // WKV scan
    k_scan<<<dim3(Hh, Bb), 64>>>(wkv_in, out_wkv);

    // LayerNorm(ys + v2)
    k_ln<<<BT, 256>>>(ln_w, ln_b);

    // Output GEMM: y = ynorm @ W_o
    k_mma_gemm<<<gemmGrid, 256, gemmSmem>>>(ynorm, W_o, out_y, BT, Cc, Cc);

    // shift state out
    k_copyshift<<<(Bb * Cc + 255) / 256, 256>>>(x, out_shift);
}

// round 4
// speedup vs baseline: 1.9211x; 1.1222x over previous
#include <cuda_runtime.h>
#include <cuda_bf16.h>
#include <cstdint>
#include <math.h>

// Problem constants
#define Bb   4
#define Tt   2048
#define Cc   2048
#define Hh   32
#define Nn   64
#define BT   (Bb*Tt)          // 8192
#define DMIX 32
#define DDEC 64
#define BIGN (BT*Cc)          // 16,777,216

// ---------------- scratch (device globals; no runtime allocation) ----------
__device__ float g_dxprev[BIGN];
__device__ float g_xxx  [BIGN];
__device__ float g_xr   [BIGN];
__device__ float g_xk   [BIGN];
__device__ float g_xv   [BIGN];
__device__ float g_xw   [BIGN];
__device__ float g_xv2  [BIGN];
__device__ float g_r    [BIGN];
__device__ float g_k    [BIGN];
__device__ float g_v    [BIGN];
__device__ float g_v2   [BIGN];
__device__ float g_decay[BIGN];
__device__ float g_ys   [BIGN];
__device__ float g_ynorm[BIGN];
__device__ float g_hpre [BT*160];
__device__ float g_tmpw [BT*DDEC];
__device__ float g_tmpv [BT*DDEC];

// ---------------- E1: token shift ------------------------------------------
__global__ void k_shift(const float* __restrict__ x,
                        const float* __restrict__ shift,
                        const float* __restrict__ maa_x) {
    int idx = blockIdx.x * 256 + threadIdx.x;
    if (idx >= BIGN) return;
    int c  = idx % Cc;
    int bt = idx / Cc;
    int t  = bt % Tt;
    int b  = bt / Tt;
    float xv   = x[idx];
    float prev = (t == 0) ? shift[b * Cc + c] : x[idx - Cc];
    float dx   = prev - xv;
    g_dxprev[idx] = dx;
    g_xxx[idx]    = xv + dx * maa_x[c];
}

// =============================================================================
// Tensor-core GEMM (bf16x3 split, fp32 accumulate)  -- unchanged from R3
// =============================================================================
#define ASTR 40
#define BSTR 136
#define SA_H 0
#define SA_L 5120
#define SB_H 10240
#define SB_L 14592
#define STG  18944
#define STG_BYTES (STG*2)

__device__ __forceinline__ void ldsm4(unsigned int* r, unsigned int addr) {
    asm volatile("ldmatrix.sync.aligned.m8n8.x4.shared.b16 {%0,%1,%2,%3},[%4];"
                 : "=r"(r[0]), "=r"(r[1]), "=r"(r[2]), "=r"(r[3]) : "r"(addr));
}
__device__ __forceinline__ void ldsm4t(unsigned int* r, unsigned int addr) {
    asm volatile("ldmatrix.sync.aligned.m8n8.x4.trans.shared.b16 {%0,%1,%2,%3},[%4];"
                 : "=r"(r[0]), "=r"(r[1]), "=r"(r[2]), "=r"(r[3]) : "r"(addr));
}
__device__ __forceinline__ void mma16816(float* c, const unsigned int* a,
                                         unsigned int b0, unsigned int b1) {
    asm volatile("mma.sync.aligned.m16n8k16.row.col.f32.bf16.bf16.f32 "
                 "{%0,%1,%2,%3},{%4,%5,%6,%7},{%8,%9},{%0,%1,%2,%3};"
                 : "+f"(c[0]), "+f"(c[1]), "+f"(c[2]), "+f"(c[3])
                 : "r"(a[0]), "r"(a[1]), "r"(a[2]), "r"(a[3]), "r"(b0), "r"(b1));
}
__device__ __forceinline__ void split2(float f, __nv_bfloat16& h, __nv_bfloat16& l) {
    h = __float2bfloat16_rn(f);
    l = __float2bfloat16_rn(f - __bfloat162float(h));
}

__global__ __launch_bounds__(256, 1)
void k_mma_gemm(const float* __restrict__ A,
                const float* __restrict__ B,
                float* __restrict__ C,
                int M, int N, int K) {
    extern __shared__ __nv_bfloat16 smbuf[];
    const int tid  = threadIdx.x;
    const int lane = tid & 31;
    const int wid  = tid >> 5;
    const int wm   = wid >> 2;
    const int wn   = wid & 3;
    const int mBase = blockIdx.y * 128;
    const int nBase = blockIdx.x * 128;

    const unsigned int smB = (unsigned int)__cvta_generic_to_shared(smbuf);

    const int arow = tid >> 3;
    const int acol = (tid & 7) * 4;
    const int brow = tid >> 5;
    const int bcol = (tid & 31) * 4;

    const float* Ap = A + (size_t)(mBase + arow) * K + acol;
    const float* Bp = B + (size_t)brow * N + nBase + bcol;

    float acc[4][4][4];
#pragma unroll
    for (int i = 0; i < 4; i++)
#pragma unroll
        for (int j = 0; j < 4; j++)
#pragma unroll
            for (int q = 0; q < 4; q++) acc[i][j][q] = 0.f;

    float4 aR[4], bR[4];
    const int kChunks = K >> 5;

#pragma unroll
    for (int p = 0; p < 4; p++) aR[p] = *(const float4*)(Ap + (size_t)(p * 32) * K);
#pragma unroll
    for (int p = 0; p < 4; p++) bR[p] = *(const float4*)(Bp + (size_t)(p * 8) * N);

    {
        __nv_bfloat16* st = smbuf;
#pragma unroll
        for (int p = 0; p < 4; p++) {
            int row = arow + p * 32;
            __nv_bfloat16 h0,h1,h2,h3,l0,l1,l2,l3;
            split2(aR[p].x,h0,l0); split2(aR[p].y,h1,l1);
            split2(aR[p].z,h2,l2); split2(aR[p].w,h3,l3);
            __nv_bfloat162 *ph = (__nv_bfloat162*)(st + SA_H + row*ASTR + acol);
            __nv_bfloat162 *pl = (__nv_bfloat162*)(st + SA_L + row*ASTR + acol);
            ph[0] = __halves2bfloat162(h0,h1); ph[1] = __halves2bfloat162(h2,h3);
            pl[0] = __halves2bfloat162(l0,l1); pl[1] = __halves2bfloat162(l2,l3);
        }
#pragma unroll
        for (int p = 0; p < 4; p++) {
            int row = brow + p * 8;
            __nv_bfloat16 h0,h1,h2,h3,l0,l1,l2,l3;
            split2(bR[p].x,h0,l0); split2(bR[p].y,h1,l1);
            split2(bR[p].z,h2,l2); split2(bR[p].w,h3,l3);
            __nv_bfloat162 *ph = (__nv_bfloat162*)(st + SB_H + row*BSTR + bcol);
            __nv_bfloat162 *pl = (__nv_bfloat162*)(st + SB_L + row*BSTR + bcol);
            ph[0] = __halves2bfloat162(h0,h1); ph[1] = __halves2bfloat162(h2,h3);
            pl[0] = __halves2bfloat162(l0,l1); pl[1] = __halves2bfloat162(l2,l3);
        }
    }
    __syncthreads();

#pragma unroll 1
    for (int ch = 0; ch < kChunks; ch++) {
        const int cur = ch & 1;
        const bool more = (ch + 1) < kChunks;

        if (more) {
            const float* Apn = Ap + (ch + 1) * 32;
            const float* Bpn = Bp + (size_t)(ch + 1) * 32 * N;
#pragma unroll
            for (int p = 0; p < 4; p++) aR[p] = *(const float4*)(Apn + (size_t)(p * 32) * K);
#pragma unroll
            for (int p = 0; p < 4; p++) bR[p] = *(const float4*)(Bpn + (size_t)(p * 8) * N);
        }

        const unsigned int sb = smB + cur * STG_BYTES;
#pragma unroll
        for (int ks = 0; ks < 2; ks++) {
            const int k0 = ks * 16;
            unsigned int ah[4][4], al[4][4], bh[2][4], bl[2][4];
#pragma unroll
            for (int mf = 0; mf < 4; mf++) {
                int row = wm * 64 + mf * 16 + (lane & 15);
                int col = k0 + (lane >> 4) * 8;
                unsigned int ad = sb + (unsigned int)(row * ASTR + col) * 2;
                ldsm4(ah[mf], ad + SA_H * 2);
                ldsm4(al[mf], ad + SA_L * 2);
            }
#pragma unroll
            for (int nf2 = 0; nf2 < 2; nf2++) {
                int rowk = k0 + (lane & 15);
                int coln = wn * 32 + nf2 * 16 + (lane >> 4) * 8;
                unsigned int bd = sb + (unsigned int)(rowk * BSTR + coln) * 2;
                ldsm4t(bh[nf2], bd + SB_H * 2);
                ldsm4t(bl[nf2], bd + SB_L * 2);
            }
#pragma unroll
            for (int mf = 0; mf < 4; mf++) {
#pragma unroll
                for (int nf = 0; nf < 4; nf++) {
                    unsigned int b0h = bh[nf >> 1][(nf & 1) * 2];
                    unsigned int b1h = bh[nf >> 1][(nf & 1) * 2 + 1];
                    unsigned int b0l = bl[nf >> 1][(nf & 1) * 2];
                    unsigned int b1l = bl[nf >> 1][(nf & 1) * 2 + 1];
                    mma16816(acc[mf][nf], ah[mf], b0h, b1h);
                    mma16816(acc[mf][nf], ah[mf], b0l, b1l);
                    mma16816(acc[mf][nf], al[mf], b0h, b1h);
                }
            }
        }

        if (more) {
            __nv_bfloat16* st = smbuf + (cur ^ 1) * STG;
#pragma unroll
            for (int p = 0; p < 4; p++) {
                int row = arow + p * 32;
                __nv_bfloat16 h0,h1,h2,h3,l0,l1,l2,l3;
                split2(aR[p].x,h0,l0); split2(aR[p].y,h1,l1);
                split2(aR[p].z,h2,l2); split2(aR[p].w,h3,l3);
                __nv_bfloat162 *ph = (__nv_bfloat162*)(st + SA_H + row*ASTR + acol);
                __nv_bfloat162 *pl = (__nv_bfloat162*)(st + SA_L + row*ASTR + acol);
                ph[0] = __halves2bfloat162(h0,h1); ph[1] = __halves2bfloat162(h2,h3);
                pl[0] = __halves2bfloat162(l0,l1); pl[1] = __halves2bfloat162(l2,l3);
            }
#pragma unroll
            for (int p = 0; p < 4; p++) {
                int row = brow + p * 8;
                __nv_bfloat16 h0,h1,h2,h3,l0,l1,l2,l3;
                split2(bR[p].x,h0,l0); split2(bR[p].y,h1,l1);
                split2(bR[p].z,h2,l2); split2(bR[p].w,h3,l3);
                __nv_bfloat162 *ph = (__nv_bfloat162*)(st + SB_H + row*BSTR + bcol);
                __nv_bfloat162 *pl = (__nv_bfloat162*)(st + SB_L + row*BSTR + bcol);
                ph[0] = __halves2bfloat162(h0,h1); ph[1] = __halves2bfloat162(h2,h3);
                pl[0] = __halves2bfloat162(l0,l1); pl[1] = __halves2bfloat162(l2,l3);
            }
        }
        __syncthreads();
    }

#pragma unroll
    for (int mf = 0; mf < 4; mf++) {
#pragma unroll
        for (int nf = 0; nf < 4; nf++) {
            int r = mBase + wm * 64 + mf * 16 + (lane >> 2);
            int c = nBase + wn * 32 + nf * 8 + (lane & 3) * 2;
            float2 v0 = make_float2(acc[mf][nf][0], acc[mf][nf][1]);
            float2 v1 = make_float2(acc[mf][nf][2], acc[mf][nf][3]);
            *(float2*)&C[(size_t)r * N + c] = v0;
            *(float2*)&C[(size_t)(r + 8) * N + c] = v1;
        }
    }
}

// ---------------- small-N fp32 GEMM: BM=32, BN=64, BK=32, 256 threads -------
// grid = ((N+63)/64, M/32). High CTA count for small N (LoRA matmuls).
__global__ __launch_bounds__(256)
void k_gemm_small(const float* __restrict__ A, int lda,
                  const float* __restrict__ B, int ldb,
                  float* __restrict__ Cd, int ldc,
                  int M, int N, int K, int act) {
    __shared__ float As[32][36];
    __shared__ float Bs[32][64];
    const int tid = threadIdx.x;
    const int mBase = blockIdx.y * 32;
    const int nBase = blockIdx.x * 64;

    const int r  = tid >> 3;        // 0..31 output row
    const int cg = tid & 7;         // col group: cols cg*8..cg*8+7

    const int arow  = tid >> 3;          // 0..31
    const int acol4 = (tid & 7) * 4;     // 0..28
    const int brow  = tid >> 4;          // 0..15 (two passes: +16)
    const int bcol4 = (tid & 15) * 4;    // 0..60

    float acc[8];
#pragma unroll
    for (int i = 0; i < 8; i++) acc[i] = 0.f;

    const float* Ab = A + (size_t)(mBase + arow) * lda + acol4;

    for (int k0 = 0; k0 < K; k0 += 32) {
        float4 a4 = *(const float4*)(Ab + k0);
        *(float4*)&As[arow][acol4] = a4;

#pragma unroll
        for (int p = 0; p < 2; p++) {
            int row = brow + p * 16;
            int col = nBase + bcol4;
            float4 b4 = make_float4(0.f, 0.f, 0.f, 0.f);
            if (col < N)
                b4 = *(const float4*)(B + (size_t)(k0 + row) * ldb + col);
            *(float4*)&Bs[row][bcol4] = b4;
        }
        __syncthreads();

#pragma unroll
        for (int kk = 0; kk < 32; kk++) {
            float a = As[r][kk];
            float4 b0 = *(const float4*)&Bs[kk][cg * 8];
            float4 b1 = *(const float4*)&Bs[kk][cg * 8 + 4];
            acc[0] += a * b0.x; acc[1] += a * b0.y;
            acc[2] += a * b0.z; acc[3] += a * b0.w;
            acc[4] += a * b1.x; acc[5] += a * b1.y;
            acc[6] += a * b1.z; acc[7] += a * b1.w;
        }
        __syncthreads();
    }

    int row = mBase + r;
#pragma unroll
    for (int j = 0; j < 8; j++) {
        int col = nBase + cg * 8 + j;
        if (col < N) {
            float vv = acc[j];
            if (act == 1) vv = tanhf(vv);
            Cd[(size_t)row * ldc + col] = vv;
        }
    }
}

// ---------------- E2: 5-way LoRA mix -> xr,xk,xv,xw,xv2 --------------------
__global__ void k_mix(const float* __restrict__ x,
                      const float* __restrict__ w2,
                      const float* __restrict__ mr, const float* __restrict__ mk,
                      const float* __restrict__ mv, const float* __restrict__ mw,
                      const float* __restrict__ mv2) {
    __shared__ float hs[32][160];
    __shared__ float ws[160][32];
    int rowBase = blockIdx.x * 32;
    int colBase = blockIdx.y * 32;
    int tid = threadIdx.x;

    for (int l = tid; l < 32 * 160; l += 256) {
        int rr = l / 160, d = l % 160;
        hs[rr][d] = g_hpre[(rowBase + rr) * 160 + d];
    }
    for (int l = tid; l < 160 * 32; l += 256) {
        int fd = l / 32, cc = l % 32;
        ws[fd][cc] = w2[fd * Cc + colBase + cc];
    }
    __syncthreads();

    int cc = tid % 32;
    int r0 = tid / 32;
    int c  = colBase + cc;
    float tr = mr[c], tk = mk[c], tv = mv[c], tw = mw[c], tv2 = mv2[c];

    for (int rr = r0; rr < 32; rr += 8) {
        float m0 = 0, m1 = 0, m2 = 0, m3 = 0, m4 = 0;
#pragma unroll
        for (int d = 0; d < 32; d++) {
            float h0 = hs[rr][d];
            float h1 = hs[rr][32 + d];
            float h2 = hs[rr][64 + d];
            float h3 = hs[rr][96 + d];
            float h4 = hs[rr][128 + d];
            m0 += h0 * ws[d][cc];
            m1 += h1 * ws[32 + d][cc];
            m2 += h2 * ws[64 + d][cc];
            m3 += h3 * ws[96 + d][cc];
            m4 += h4 * ws[128 + d][cc];
        }
        int idx = (rowBase + rr) * Cc + c;
        float xv = x[idx], dx = g_dxprev[idx];
        g_xr[idx]  = xv + dx * (tr  + m0);
        g_xk[idx]  = xv + dx * (tk  + m1);
        g_xv[idx]  = xv + dx * (tv  + m2);
        g_xw[idx]  = xv + dx * (tw  + m3);
        g_xv2[idx] = xv + dx * (tv2 + m4);
    }
}

// ---------------- E3: decay ---------------------------------------------------
__global__ void k_decay(const float* __restrict__ tdec,
                        const float* __restrict__ w2) {
    __shared__ float tw[32][64];
    __shared__ float w2s[64][64];
    int rowBase = blockIdx.x * 32;
    int colBase = blockIdx.y * 64;
    int tid = threadIdx.x;

    for (int l = tid; l < 32 * 64; l += 256) {
        int rr = l / 64, d = l % 64;
        tw[rr][d] = g_tmpw[(rowBase + rr) * 64 + d];
    }
    for (int l = tid; l < 64 * 64; l += 256) {
        int d = l / 64, cc = l % 64;
        w2s[d][cc] = w2[d * Cc + colBase + cc];
    }
    __syncthreads();

    int cc = tid % 64;
    int r0 = tid / 64;
    float td = tdec[colBase + cc];
    for (int rr = r0; rr < 32; rr += 4) {
        float s = td;
#pragma unroll
        for (int d = 0; d < 64; d++) s += tw[rr][d] * w2s[d][cc];
        float dec = expf(-expf(s));
        int idx = (rowBase + rr) * Cc + colBase + cc;
        g_decay[idx] = dec;
        g_k[idx] *= (1.f - dec);
    }
}

// ---------------- E4: v2 += tmpv @ value2_w2 --------------------------------
__global__ void k_v2add(const float* __restrict__ w2) {
    __shared__ float tw[32][64];
    __shared__ float w2s[64][64];
    int rowBase = blockIdx.x * 32;
    int colBase = blockIdx.y * 64;
    int tid = threadIdx.x;

    for (int l = tid; l < 32 * 64; l += 256) {
        int rr = l / 64, d = l % 64;
        tw[rr][d] = g_tmpv[(rowBase + rr) * 64 + d];
    }
    for (int l = tid; l < 64 * 64; l += 256) {
        int d = l / 64, cc = l % 64;
        w2s[d][cc] = w2[d * Cc + colBase + cc];
    }
    __syncthreads();

    int cc = tid % 64;
    int r0 = tid / 64;
    for (int rr = r0; rr < 32; rr += 4) {
        float s = 0.f;
#pragma unroll
        for (int d = 0; d < 64; d++) s += tw[rr][d] * w2s[d][cc];
        int idx = (rowBase + rr) * Cc + colBase + cc;
        g_v2[idx] += s;
    }
}

// ---------------- S: WKV scan, chunked cp.async double-buffered -------------
// block = (h, b), 64 threads. CHUNK timesteps of r/k/decay/v prefetched into
// the shadow smem buffer while computing the current chunk.
#define CHUNK 8
__device__ __forceinline__ void cpasync16(unsigned int daddr, const float* gp) {
    asm volatile("cp.async.ca.shared.global [%0], [%1], 16;"
                 :: "r"(daddr), "l"(gp));
}

__global__ __launch_bounds__(64)
void k_scan(const float* __restrict__ wkv_in,
            float* __restrict__ wkv_out) {
    const int h = blockIdx.x, b = blockIdx.y;
    const int j = threadIdx.x;

    __shared__ float sbuf[2][4][CHUNK][64];   // [buf][arr: r,k,d,v][t][i]
    const unsigned int sb = (unsigned int)__cvta_generic_to_shared(&sbuf[0][0][0][0]);

    float state[64];
#pragma unroll
    for (int i = 0; i < 64; i++)
        state[i] = wkv_in[(size_t)((b * Hh + h) * Nn + i) * Nn + j];

    const float* srcs[4] = { g_r, g_k, g_decay, g_v };
    const size_t rowOff = (size_t)h * Nn;

    // issue loads for chunk starting at t0 into buffer `buf`
    auto issue = [&](int buf, int t0) {
#pragma unroll
        for (int p = 0; p < 8; p++) {
            int l   = threadIdx.x + 64 * p;   // 0..511
            int arr = l >> 7;
            int rem = l & 127;
            int t   = rem >> 4;
            int seg = rem & 15;
            const float* gp = srcs[arr] +
                (size_t)(b * Tt + t0 + t) * Cc + rowOff + seg * 4;
            unsigned int da = sb +
                (unsigned int)((((buf * 4 + arr) * CHUNK + t) * 64) + seg * 4) * 4;
            cpasync16(da, gp);
        }
        asm volatile("cp.async.commit_group;");
    };

    issue(0, 0);
    asm volatile("cp.async.wait_group 0;" ::: "memory");
    __syncthreads();

    const int nch = Tt / CHUNK;
    for (int ch = 0; ch < nch; ch++) {
        const int cur = ch & 1;
        if (ch + 1 < nch) issue(cur ^ 1, (ch + 1) * CHUNK);

        const int t0 = ch * CHUNK;
#pragma unroll
        for (int tt = 0; tt < CHUNK; tt++) {
            const float4* rs4 = (const float4*)&sbuf[cur][0][tt][0];
            const float4* ks4 = (const float4*)&sbuf[cur][1][tt][0];
            const float4* ds4 = (const float4*)&sbuf[cur][2][tt][0];
            const float vj = sbuf[cur][3][tt][j];

            float y = 0.f;
#pragma unroll
            for (int i4 = 0; i4 < 16; i4++) {
                float4 r4 = rs4[i4], k4 = ks4[i4], d4 = ds4[i4];
                float s0 = state[4*i4+0], s1 = state[4*i4+1];
                float s2 = state[4*i4+2], s3 = state[4*i4+3];
                y += r4.x * s0; y += r4.y * s1;
                y += r4.z * s2; y += r4.w * s3;
                state[4*i4+0] = s0 * d4.x + k4.x * vj;
                state[4*i4+1] = s1 * d4.y + k4.y * vj;
                state[4*i4+2] = s2 * d4.z + k4.z * vj;
                state[4*i4+3] = s3 * d4.w + k4.w * vj;
            }
            g_ys[(size_t)(b * Tt + t0 + tt) * Cc + rowOff + j] = y;
        }

        asm volatile("cp.async.wait_group 0;" ::: "memory");
        __syncthreads();
    }

#pragma unroll
    for (int i = 0; i < 64; i++)
        wkv_out[(size_t)((b * Hh + h) * Nn + i) * Nn + j] = state[i];
}

// ---------------- E5: y = LN(ys + v2) ---------------------------------------
__global__ void k_ln(const float* __restrict__ lnw,
                     const float* __restrict__ lnb) {
    int row = blockIdx.x;
    int tid = threadIdx.x;
    const float* a = g_ys + (size_t)row * Cc;
    const float* bp = g_v2 + (size_t)row * Cc;
    float s = 0.f, ss = 0.f;
    for (int c = tid; c < Cc; c += 256) {
        float v = a[c] + bp[c];
        s += v; ss += v * v;
    }
    __shared__ float sh1[256], sh2[256];
    sh1[tid] = s; sh2[tid] = ss;
    __syncthreads();
    for (int st = 128; st > 0; st >>= 1) {
        if (tid < st) { sh1[tid] += sh1[tid + st]; sh2[tid] += sh2[tid + st]; }
        __syncthreads();
    }
    float mu  = sh1[0] / Cc;
    float var = sh2[0] / Cc - mu * mu;
    float rstd = rsqrtf(var + 1e-5f);
    for (int c = tid; c < Cc; c += 256) {
        float v = a[c] + bp[c];
        g_ynorm[(size_t)row * Cc + c] = (v - mu) * rstd * lnw[c] + lnb[c];
    }
}

// ---------------- E6: shift_state_out ---------------------------------------
__global__ void k_copyshift(const float* __restrict__ x, float* __restrict__ out) {
    int i = blockIdx.x * 256 + threadIdx.x;
    if (i >= Bb * Cc) return;
    int b = i / Cc, c = i % Cc;
    out[i] = x[(size_t)(b * Tt + Tt - 1) * Cc + c];
}

// ---------------- launcher ---------------------------------------------------
extern "C" void kernel_launch(void* const* d_in, const int* in_sizes, int n_in,
                              void* d_out, int out_size) {
    const float* x        = (const float*)d_in[0];
    const float* shift_in = (const float*)d_in[1];
    const float* wkv_in   = (const float*)d_in[2];
    const float* maa_x    = (const float*)d_in[3];
    const float* maa_r    = (const float*)d_in[4];
    const float* maa_k    = (const float*)d_in[5];
    const float* maa_v    = (const float*)d_in[6];
    const float* maa_w    = (const float*)d_in[7];
    const float* maa_v2   = (const float*)d_in[8];
    const float* maa_w1   = (const float*)d_in[9];
    const float* maa_w2   = (const float*)d_in[10];
    const float* tdecay   = (const float*)d_in[11];
    const float* dec_w1   = (const float*)d_in[12];
    const float* dec_w2   = (const float*)d_in[13];
    const float* v2_w1    = (const float*)d_in[14];
    const float* v2_w2    = (const float*)d_in[15];
    const float* W_r      = (const float*)d_in[16];
    const float* W_k      = (const float*)d_in[17];
    const float* W_v      = (const float*)d_in[18];
    const float* W_o      = (const float*)d_in[19];
    const float* ln_w     = (const float*)d_in[20];
    const float* ln_b     = (const float*)d_in[21];

    float* out_y     = (float*)d_out;
    float* out_shift = out_y + (size_t)BT * Cc;
    float* out_wkv   = out_shift + (size_t)Bb * Cc;

    float *xxx = 0, *xr = 0, *xk = 0, *xv = 0, *xw = 0, *xv2 = 0;
    float *rb = 0, *kb = 0, *vb = 0, *v2b = 0, *hpre = 0, *tmpw = 0, *tmpv = 0, *ynorm = 0;
    cudaGetSymbolAddress((void**)&xxx,    g_xxx);
    cudaGetSymbolAddress((void**)&xr,     g_xr);
    cudaGetSymbolAddress((void**)&xk,     g_xk);
    cudaGetSymbolAddress((void**)&xv,     g_xv);
    cudaGetSymbolAddress((void**)&xw,     g_xw);
    cudaGetSymbolAddress((void**)&xv2,    g_xv2);
    cudaGetSymbolAddress((void**)&rb,     g_r);
    cudaGetSymbolAddress((void**)&kb,     g_k);
    cudaGetSymbolAddress((void**)&vb,     g_v);
    cudaGetSymbolAddress((void**)&v2b,    g_v2);
    cudaGetSymbolAddress((void**)&hpre,   g_hpre);
    cudaGetSymbolAddress((void**)&tmpw,   g_tmpw);
    cudaGetSymbolAddress((void**)&tmpv,   g_tmpv);
    cudaGetSymbolAddress((void**)&ynorm,  g_ynorm);

    cudaFuncSetAttribute(k_mma_gemm,
                         cudaFuncAttributeMaxDynamicSharedMemorySize,
                         2 * STG_BYTES);

    const dim3 gemmGrid(Cc / 128, BT / 128);
    const int  gemmSmem = 2 * STG_BYTES;

    // E1: token shift
    k_shift<<<BIGN / 256, 256>>>(x, shift_in, maa_x);

    // G1: hpre = tanh(xxx @ maa_w1)  [8192,160]
    k_gemm_small<<<dim3(3, BT / 32), 256>>>(xxx, Cc, maa_w1, 160, hpre, 160,
                                            BT, 160, Cc, 1);

    // E2: 5-way mix
    k_mix<<<dim3(BT / 32, Cc / 32), 256>>>(x, maa_w2, maa_r, maa_k, maa_v,
                                           maa_w, maa_v2);

    // Big GEMMs on tensor cores (bf16x3)
    k_mma_gemm<<<gemmGrid, 256, gemmSmem>>>(xr,  W_r, rb,  BT, Cc, Cc);
    k_mma_gemm<<<gemmGrid, 256, gemmSmem>>>(xk,  W_k, kb,  BT, Cc, Cc);
    k_mma_gemm<<<gemmGrid, 256, gemmSmem>>>(xv,  W_v, vb,  BT, Cc, Cc);
    k_mma_gemm<<<gemmGrid, 256, gemmSmem>>>(xv2, W_v, v2b, BT, Cc, Cc);

    // Small LoRA GEMMs (tanh)
    k_gemm_small<<<dim3(1, BT / 32), 256>>>(xw,  Cc, dec_w1, 64, tmpw, 64,
                                            BT, 64, Cc, 1);
    k_gemm_small<<<dim3(1, BT / 32), 256>>>(xv2, Cc, v2_w1,  64, tmpv, 64,
                                            BT, 64, Cc, 1);

    // E3/E4 epilogues
    k_decay<<<dim3(BT / 32, Cc / 64), 256>>>(tdecay, dec_w2);
    k_v2add<<<dim3(BT / 32, Cc / 64), 256>>>(v2_w2);

    // WKV scan
    k_scan<<<dim3(Hh, Bb), 64>>>(wkv_in, out_wkv);

    // LayerNorm(ys + v2)
    k_ln<<<BT, 256>>>(ln_w, ln_b);

    // Output GEMM: y = ynorm @ W_o
    k_mma_gemm<<<gemmGrid, 256, gemmSmem>>>(ynorm, W_o, out_y, BT, Cc, Cc);

    // shift state out
    k_copyshift<<<(Bb * Cc + 255) / 256, 256>>>(x, out_shift);
}